// round 2
// baseline (speedup 1.0000x reference)
#include <cuda_runtime.h>
#include <stdint.h>

#define BATCH 32
#define T 2048
#define BUCKETS 4000000ULL
#define NTOT (BATCH * T)

__constant__ unsigned long long c_primes[8] = {
    2654435761ULL, 2246822519ULL, 3266489917ULL, 2028178513ULL,
    1220703125ULL, 1610612741ULL, 805306457ULL,  402653189ULL
};

// 1 => tokens buffer is int64 (read word 2*i), 0 => int32 (read word i)
__device__ int g_is64;

__global__ void detect_dtype_kernel(const unsigned int* __restrict__ p)
{
    __shared__ int found;
    if (threadIdx.x == 0) found = 0;
    __syncthreads();
    int f = 0;
    // scan odd 32-bit words of the first 65536 words (safe for both layouts)
    for (int i = 1 + 2 * threadIdx.x; i < 65536; i += 2 * blockDim.x)
        if (p[i] != 0u) f = 1;
    if (f) atomicOr(&found, 1);
    __syncthreads();
    if (threadIdx.x == 0) g_is64 = found ? 0 : 1;
}

__global__ __launch_bounds__(256)
void pyramid_kernel(const unsigned int* __restrict__ tok32,
                    const float4* __restrict__ tab0,
                    const float4* __restrict__ tab1,
                    const float4* __restrict__ tab2,
                    const float4* __restrict__ tab3,
                    const float* __restrict__ cond_w,
                    float4* __restrict__ out)
{
    __shared__ float w[64];
    if (threadIdx.x < 64) w[threadIdx.x] = cond_w[threadIdx.x];
    __syncthreads();

    const int shift = g_is64;   // index scaling: int64 -> 2*i, int32 -> i

    int idx = blockIdx.x * 256 + threadIdx.x;
    if (idx >= NTOT) return;
    int t = idx & (T - 1);
    int b = idx >> 11;           // T = 2048
    const unsigned int* row = tok32 + ((size_t)b * T << shift);

    // rolling XOR-hash; window-w key is the prefix after w terms
    unsigned long long h = 0ULL, h0 = 0ULL, h1 = 0ULL, h2 = 0ULL, h3 = 0ULL;
#pragma unroll
    for (int i = 0; i < 8; i++) {
        int src = t - 1 - i;
        unsigned long long tok =
            (src >= 0) ? (unsigned long long)row[src << shift] : 0ULL;
        h ^= tok * c_primes[i];
        if (i == 0) h0 = h;
        if (i == 1) h1 = h;
        if (i == 3) h2 = h;
        if (i == 7) h3 = h;
    }
    unsigned int k0 = (unsigned int)(h0 % BUCKETS);
    unsigned int k1 = (unsigned int)(h1 % BUCKETS);
    unsigned int k2 = (unsigned int)(h2 % BUCKETS);
    unsigned int k3 = (unsigned int)(h3 % BUCKETS);

    // short gathers (independent -> MLP=2)
    float4 e0 = __ldg(&tab0[k0]);
    float4 e1 = __ldg(&tab1[k1]);

    float cat[8] = { e0.x, e0.y, e0.z, e0.w, e1.x, e1.y, e1.z, e1.w };

    // sign-LSH: sequential fma chain in d-order to match reference fp order
    unsigned long long ck = 0ULL;
#pragma unroll
    for (int o = 0; o < 8; o++) {
        float acc = 0.0f;
#pragma unroll
        for (int d = 0; d < 8; d++)
            acc = fmaf(cat[d], w[o * 8 + d], acc);
        if (acc > 0.0f) ck ^= c_primes[o];
    }

    unsigned int kk2 = (unsigned int)(((unsigned long long)k2 ^ ck) % BUCKETS);
    unsigned int kk3 = (unsigned int)(((unsigned long long)k3 ^ ck) % BUCKETS);

    float4 e2 = __ldg(&tab2[kk2]);
    float4 e3 = __ldg(&tab3[kk3]);

    size_t base = (size_t)idx * 4;
    out[base + 0] = e0;
    out[base + 1] = e1;
    out[base + 2] = e2;
    out[base + 3] = e3;
}

extern "C" void kernel_launch(void* const* d_in, const int* in_sizes, int n_in,
                              void* d_out, int out_size)
{
    // Resolve inputs by element count (robust to metadata ordering):
    //   tokens = 65536, each table = 16,000,000, cond_w = 64
    const void* tokens = 0;
    const void* tabs[4] = {0, 0, 0, 0};
    const void* cw = 0;
    int nt = 0;
    for (int i = 0; i < n_in; i++) {
        if (in_sizes[i] == 64) cw = d_in[i];
        else if (in_sizes[i] == 16000000) { if (nt < 4) tabs[nt++] = d_in[i]; }
        else if (in_sizes[i] == BATCH * T) tokens = d_in[i];
    }

    detect_dtype_kernel<<<1, 256>>>((const unsigned int*)tokens);
    pyramid_kernel<<<NTOT / 256, 256>>>(
        (const unsigned int*)tokens,
        (const float4*)tabs[0], (const float4*)tabs[1],
        (const float4*)tabs[2], (const float4*)tabs[3],
        (const float*)cw, (float4*)d_out);
}

// round 3
// speedup vs baseline: 1.2149x; 1.2149x over previous
#include <cuda_runtime.h>
#include <stdint.h>

#define BATCH 32
#define T 2048
#define BUCKETS 4000000ULL
#define NTOT (BATCH * T)

__constant__ unsigned long long c_primes[8] = {
    2654435761ULL, 2246822519ULL, 3266489917ULL, 2028178513ULL,
    1220703125ULL, 1610612741ULL, 805306457ULL,  402653189ULL
};

// 1 => tokens buffer is int64 (stride-2 32-bit words), 0 => int32
__device__ int g_is64;

__global__ void detect_dtype_kernel(const unsigned int* __restrict__ p)
{
    // one warp: if tokens are int32, odd words are real tokens (all-zero prob 2^-320)
    unsigned int v = p[1 + 2 * threadIdx.x];
    unsigned int bal = __ballot_sync(0xffffffffu, v != 0u);
    if (threadIdx.x == 0) g_is64 = (bal == 0u) ? 1 : 0;
}

__device__ __forceinline__ void hash_keys(const unsigned int* s_tok, int j,
                                          unsigned int& k0, unsigned int& k1,
                                          unsigned int& k2, unsigned int& k3)
{
    // s_tok[8 + j] corresponds to position t; window terms are s_tok[8+j-1-i]
    unsigned long long h = 0ULL, h0, h1, h2, h3;
#pragma unroll
    for (int i = 0; i < 8; i++) {
        unsigned long long tok = (unsigned long long)s_tok[8 + j - 1 - i];
        h ^= tok * c_primes[i];
        if (i == 0) h0 = h;
        if (i == 1) h1 = h;
        if (i == 3) h2 = h;
        if (i == 7) h3 = h;
    }
    k0 = (unsigned int)(h0 % BUCKETS);
    k1 = (unsigned int)(h1 % BUCKETS);
    k2 = (unsigned int)(h2 % BUCKETS);
    k3 = (unsigned int)(h3 % BUCKETS);
}

__device__ __forceinline__ unsigned long long lsh_key(const float4& e0, const float4& e1,
                                                      const float* w)
{
    float cat[8] = { e0.x, e0.y, e0.z, e0.w, e1.x, e1.y, e1.z, e1.w };
    unsigned long long ck = 0ULL;
#pragma unroll
    for (int o = 0; o < 8; o++) {
        float acc = 0.0f;
#pragma unroll
        for (int d = 0; d < 8; d++)
            acc = fmaf(cat[d], w[o * 8 + d], acc);
        if (acc > 0.0f) ck ^= c_primes[o];
    }
    return ck;
}

// 128 threads/block, 2 positions/thread, 256 positions/block -> 256 blocks
__global__ __launch_bounds__(128)
void pyramid_kernel(const unsigned int* __restrict__ tok32,
                    const float4* __restrict__ tab0,
                    const float4* __restrict__ tab1,
                    const float4* __restrict__ tab2,
                    const float4* __restrict__ tab3,
                    const float* __restrict__ cond_w,
                    float4* __restrict__ out)
{
    __shared__ float w[64];
    __shared__ unsigned int s_tok[8 + 256];

    const int tid = threadIdx.x;
    if (tid < 64) w[tid] = cond_w[tid];

    const int shift = g_is64;
    const int B0 = blockIdx.x * 256;        // first global position of block
    const int b  = B0 >> 11;                // T = 2048
    const int t0 = B0 & (T - 1);            // multiple of 256 -> 0 or >= 256
    const unsigned int* row = tok32 + ((size_t)b * T << shift);

    // stage tokens [t0-8, t0+256) ; t<0 -> 0 (pad)
    for (int j = tid; j < 264; j += 128) {
        int t = t0 + j - 8;
        s_tok[j] = (t >= 0) ? row[(size_t)t << shift] : 0u;
    }
    __syncthreads();

    const int j0 = tid * 2;       // local positions j0, j0+1

    unsigned int k0a, k1a, k2a, k3a, k0b, k1b, k2b, k3b;
    hash_keys(s_tok, j0,     k0a, k1a, k2a, k3a);
    hash_keys(s_tok, j0 + 1, k0b, k1b, k2b, k3b);

    // 4 independent short gathers
    float4 e0a = __ldg(&tab0[k0a]);
    float4 e1a = __ldg(&tab1[k1a]);
    float4 e0b = __ldg(&tab0[k0b]);
    float4 e1b = __ldg(&tab1[k1b]);

    unsigned long long cka = lsh_key(e0a, e1a, w);
    unsigned long long ckb = lsh_key(e0b, e1b, w);

    unsigned int kk2a = (unsigned int)(((unsigned long long)k2a ^ cka) % BUCKETS);
    unsigned int kk3a = (unsigned int)(((unsigned long long)k3a ^ cka) % BUCKETS);
    unsigned int kk2b = (unsigned int)(((unsigned long long)k2b ^ ckb) % BUCKETS);
    unsigned int kk3b = (unsigned int)(((unsigned long long)k3b ^ ckb) % BUCKETS);

    // 4 independent long gathers
    float4 e2a = __ldg(&tab2[kk2a]);
    float4 e3a = __ldg(&tab3[kk3a]);
    float4 e2b = __ldg(&tab2[kk2b]);
    float4 e3b = __ldg(&tab3[kk3b]);

    // 128B contiguous store per thread (one full L2 line)
    size_t base = ((size_t)(B0 + j0)) * 4;
    out[base + 0] = e0a;
    out[base + 1] = e1a;
    out[base + 2] = e2a;
    out[base + 3] = e3a;
    out[base + 4] = e0b;
    out[base + 5] = e1b;
    out[base + 6] = e2b;
    out[base + 7] = e3b;
}

extern "C" void kernel_launch(void* const* d_in, const int* in_sizes, int n_in,
                              void* d_out, int out_size)
{
    // Resolve inputs by element count (robust to metadata ordering):
    //   tokens = 65536, each table = 16,000,000, cond_w = 64
    const void* tokens = 0;
    const void* tabs[4] = {0, 0, 0, 0};
    const void* cw = 0;
    int nt = 0;
    for (int i = 0; i < n_in; i++) {
        if (in_sizes[i] == 64) cw = d_in[i];
        else if (in_sizes[i] == 16000000) { if (nt < 4) tabs[nt++] = d_in[i]; }
        else if (in_sizes[i] == BATCH * T) tokens = d_in[i];
    }

    detect_dtype_kernel<<<1, 32>>>((const unsigned int*)tokens);
    pyramid_kernel<<<NTOT / 256, 128>>>(
        (const unsigned int*)tokens,
        (const float4*)tabs[0], (const float4*)tabs[1],
        (const float4*)tabs[2], (const float4*)tabs[3],
        (const float*)cw, (float4*)d_out);
}